// round 8
// baseline (speedup 1.0000x reference)
#include <cuda_runtime.h>
#include <cuda_bf16.h>
#include <cstdint>
#include <cstddef>

// Problem constants
#define T_STEPS 100
#define B_DIM   512
#define I_DIM   512
#define O_DIM   512
#define M_DIM   (T_STEPS * B_DIM)   // 51200
#define BO      (B_DIM * O_DIM)     // 262144

#define BETA_F   0.9f
#define THRESH_F 1.0f
#define DELTA_MEM 3e-4f             // flag margin: 10x bound on |cur_tc - cur_seq|

// Scratch for input currents cur[T, B, O] (105 MB)
__device__ float g_cur[(size_t)T_STEPS * B_DIM * O_DIM];
// Flag worklist of ambiguous neurons (bo indices)
__device__ int g_flag_list[BO];
__device__ int g_flag_cnt;

// ---------------------------------------------------------------------------
// bf16x3 exact-fp32 GEMM on legacy tensor cores (mma.sync, sm_100 base ISA)
// ---------------------------------------------------------------------------
#define KC        64
#define NKC       (I_DIM / KC)        // 8
#define TILE_B    (128 * 128)
#define BUF_B     (6 * TILE_B)        // 98304 B
#define SMEM_ASK  (1024 + 2 * BUF_B)

static __device__ __forceinline__ uint32_t smem_u32(const void* p) {
    uint32_t a;
    asm("{ .reg .u64 t; cvta.to.shared.u64 t, %1; cvt.u32.u64 %0, t; }"
        : "=r"(a) : "l"(p));
    return a;
}

#define LDSM4(r0, r1, r2, r3, addr) \
    asm volatile("ldmatrix.sync.aligned.m8n8.x4.shared.b16 {%0,%1,%2,%3}, [%4];" \
        : "=r"(r0), "=r"(r1), "=r"(r2), "=r"(r3) : "r"(addr))

#define MMA_OP(D, A, b0, b1) \
    asm volatile("mma.sync.aligned.m16n8k16.row.col.f32.bf16.bf16.f32 " \
        "{%0,%1,%2,%3}, {%4,%5,%6,%7}, {%8,%9}, {%0,%1,%2,%3};" \
        : "+f"((D)[0]), "+f"((D)[1]), "+f"((D)[2]), "+f"((D)[3]) \
        : "r"((A)[0]), "r"((A)[1]), "r"((A)[2]), "r"((A)[3]), "r"(b0), "r"(b1))

static __device__ __forceinline__ uint32_t pack2(__nv_bfloat16 lo, __nv_bfloat16 hi) {
    __nv_bfloat162 p = __halves2bfloat162(lo, hi);
    return *reinterpret_cast<uint32_t*>(&p);
}

static __device__ __forceinline__ void split_store(char* tile0, uint32_t sw, float4 v) {
    float f0 = v.x, f1 = v.y, f2 = v.z, f3 = v.w;

    __nv_bfloat16 a0 = __float2bfloat16_rn(f0);
    __nv_bfloat16 a1 = __float2bfloat16_rn(f1);
    __nv_bfloat16 a2 = __float2bfloat16_rn(f2);
    __nv_bfloat16 a3 = __float2bfloat16_rn(f3);

    float r0 = f0 - __bfloat162float(a0);
    float r1 = f1 - __bfloat162float(a1);
    float r2 = f2 - __bfloat162float(a2);
    float r3 = f3 - __bfloat162float(a3);

    __nv_bfloat16 b0 = __float2bfloat16_rn(r0);
    __nv_bfloat16 b1 = __float2bfloat16_rn(r1);
    __nv_bfloat16 b2 = __float2bfloat16_rn(r2);
    __nv_bfloat16 b3 = __float2bfloat16_rn(r3);

    float s0 = r0 - __bfloat162float(b0);
    float s1 = r1 - __bfloat162float(b1);
    float s2 = r2 - __bfloat162float(b2);
    float s3 = r3 - __bfloat162float(b3);

    __nv_bfloat16 c0 = __float2bfloat16_rn(s0);
    __nv_bfloat16 c1 = __float2bfloat16_rn(s1);
    __nv_bfloat16 c2 = __float2bfloat16_rn(s2);
    __nv_bfloat16 c3 = __float2bfloat16_rn(s3);

    uint2 w1; w1.x = pack2(a0, a1); w1.y = pack2(a2, a3);
    uint2 w2; w2.x = pack2(b0, b1); w2.y = pack2(b2, b3);
    uint2 w3; w3.x = pack2(c0, c1); w3.y = pack2(c2, c3);

    *reinterpret_cast<uint2*>(tile0 + sw)              = w1;
    *reinterpret_cast<uint2*>(tile0 + TILE_B + sw)     = w2;
    *reinterpret_cast<uint2*>(tile0 + 2 * TILE_B + sw) = w3;
}

__global__ void __launch_bounds__(256)
snn_gemm_mma(const float* __restrict__ X, const float* __restrict__ Wm,
             const float* __restrict__ bias)
{
    extern __shared__ char smraw[];
    char* sm = (char*)((((uintptr_t)smraw) + 1023) & ~(uintptr_t)1023);
    const uint32_t sb = smem_u32(sm);

    const int tid  = threadIdx.x;
    const int warp = tid >> 5;
    const int lane = tid & 31;
    const int wm   = warp & 3;
    const int wn   = warp >> 2;

    const int n0 = blockIdx.x * 128;
    const int m0 = blockIdx.y * 128;

    const float* xs0 = X  + (size_t)m0 * I_DIM;
    const float* ws0 = Wm + (size_t)n0 * I_DIM;

    float acc[2][8][4] = {};
    float4 px[8], pw[8];

    auto loadc = [&](int kc) {
        #pragma unroll
        for (int i = 0; i < 8; ++i) {
            const int v   = i * 256 + tid;
            const int row = v >> 4;
            const int col = (v & 15) << 2;
            px[i] = *reinterpret_cast<const float4*>(
                xs0 + (size_t)row * I_DIM + kc * KC + col);
            pw[i] = *reinterpret_cast<const float4*>(
                ws0 + (size_t)row * I_DIM + kc * KC + col);
        }
    };

    auto storec = [&](char* bb) {
        #pragma unroll
        for (int i = 0; i < 8; ++i) {
            const int v   = i * 256 + tid;
            const int row = v >> 4;
            const int col = (v & 15) << 2;
            const uint32_t off = (uint32_t)(row * 128 + col * 2);
            const uint32_t sw  = off ^ ((off >> 3) & 0x70);
            split_store(bb, sw, px[i]);
            split_store(bb + 3 * TILE_B, sw, pw[i]);
        }
    };

    auto mmac = [&](uint32_t bbu) {
        const int PA[6] = {0, 0, 1, 1, 0, 2};
        const int PB[6] = {0, 1, 0, 1, 2, 0};
        #pragma unroll
        for (int p = 0; p < 6; ++p) {
            const uint32_t At = bbu + PA[p] * TILE_B;
            const uint32_t Bt = bbu + (3 + PB[p]) * TILE_B;
            #pragma unroll
            for (int ks = 0; ks < 4; ++ks) {
                uint32_t a[2][4];
                #pragma unroll
                for (int mt = 0; mt < 2; ++mt) {
                    const int row = wm * 32 + mt * 16 + (lane & 15);
                    const uint32_t off = (uint32_t)(row * 128 + ks * 32 + ((lane >> 4) << 4));
                    const uint32_t ad  = At + (off ^ ((off >> 3) & 0x70));
                    LDSM4(a[mt][0], a[mt][1], a[mt][2], a[mt][3], ad);
                }
                #pragma unroll
                for (int nq = 0; nq < 4; ++nq) {
                    const int g = lane >> 3, r = lane & 7;
                    const int nrow = wn * 64 + nq * 16 + ((g >> 1) << 3) + r;
                    const uint32_t off = (uint32_t)(nrow * 128 + ks * 32 + ((g & 1) << 4));
                    const uint32_t ad  = Bt + (off ^ ((off >> 3) & 0x70));
                    uint32_t b0, b1, b2, b3;
                    LDSM4(b0, b1, b2, b3, ad);
                    MMA_OP(acc[0][2 * nq],     a[0], b0, b1);
                    MMA_OP(acc[1][2 * nq],     a[1], b0, b1);
                    MMA_OP(acc[0][2 * nq + 1], a[0], b2, b3);
                    MMA_OP(acc[1][2 * nq + 1], a[1], b2, b3);
                }
            }
        }
    };

    loadc(0);
    for (int kc = 0; kc < NKC; ++kc) {
        char*    bb  = sm + (kc & 1) * BUF_B;
        uint32_t bbu = sb + (kc & 1) * BUF_B;
        storec(bb);
        __syncthreads();
        if (kc + 1 < NKC) loadc(kc + 1);
        mmac(bbu);
    }

    {
        const int rbase = m0 + wm * 32 + (lane >> 2);
        const int nb    = n0 + wn * 64 + (lane & 3) * 2;
        #pragma unroll
        for (int nt = 0; nt < 8; ++nt) {
            const int n = nb + nt * 8;
            const float2 bv = *reinterpret_cast<const float2*>(bias + n);
            #pragma unroll
            for (int mt = 0; mt < 2; ++mt) {
                const int r0 = rbase + mt * 16;
                float2 o0, o1;
                o0.x = acc[mt][nt][0] + bv.x;
                o0.y = acc[mt][nt][1] + bv.y;
                o1.x = acc[mt][nt][2] + bv.x;
                o1.y = acc[mt][nt][3] + bv.y;
                *reinterpret_cast<float2*>(&g_cur[(size_t)r0 * O_DIM + n])       = o0;
                *reinterpret_cast<float2*>(&g_cur[(size_t)(r0 + 8) * O_DIM + n]) = o1;
            }
        }
    }
}

// ---------------------------------------------------------------------------
// Zero the flag counter (replaces host cudaMemsetAsync; pure kernel node).
// ---------------------------------------------------------------------------
__global__ void snn_zero() { g_flag_cnt = 0; }

// ---------------------------------------------------------------------------
// Scan + ambiguity flagging. Neurons whose decision margin ever falls inside
// +-DELTA_MEM get pushed to the repair worklist (single aggregated atomic).
// ---------------------------------------------------------------------------
__global__ __launch_bounds__(256)
void snn_scan_flag(float* __restrict__ out) {
    const int lane4 = blockIdx.x * blockDim.x + threadIdx.x;
    const size_t base = (size_t)lane4 * 4;

    float4 mem = make_float4(0.f, 0.f, 0.f, 0.f);
    int fl0 = 0, fl1 = 0, fl2 = 0, fl3 = 0;

    #pragma unroll 5
    for (int t = 0; t < T_STEPS; ++t) {
        const size_t off = (size_t)t * BO + base;
        float4 c = *reinterpret_cast<const float4*>(&g_cur[off]);

        mem.x = BETA_F * mem.x + c.x;
        mem.y = BETA_F * mem.y + c.y;
        mem.z = BETA_F * mem.z + c.z;
        mem.w = BETA_F * mem.w + c.w;

        fl0 |= (fabsf(mem.x - THRESH_F) < DELTA_MEM);
        fl1 |= (fabsf(mem.y - THRESH_F) < DELTA_MEM);
        fl2 |= (fabsf(mem.z - THRESH_F) < DELTA_MEM);
        fl3 |= (fabsf(mem.w - THRESH_F) < DELTA_MEM);

        float4 spk;
        spk.x = (mem.x >= THRESH_F) ? 1.0f : 0.0f;
        spk.y = (mem.y >= THRESH_F) ? 1.0f : 0.0f;
        spk.z = (mem.z >= THRESH_F) ? 1.0f : 0.0f;
        spk.w = (mem.w >= THRESH_F) ? 1.0f : 0.0f;

        *reinterpret_cast<float4*>(&out[off]) = spk;

        mem.x -= spk.x * THRESH_F;
        mem.y -= spk.y * THRESH_F;
        mem.z -= spk.z * THRESH_F;
        mem.w -= spk.w * THRESH_F;
    }

    const int nf = fl0 + fl1 + fl2 + fl3;
    if (nf) {
        int pos = atomicAdd(&g_flag_cnt, nf);   // one atomic per flagging thread
        if (fl0) g_flag_list[pos++] = (int)base + 0;
        if (fl1) g_flag_list[pos++] = (int)base + 1;
        if (fl2) g_flag_list[pos++] = (int)base + 2;
        if (fl3) g_flag_list[pos++] = (int)base + 3;
    }
}

// ---------------------------------------------------------------------------
// Repair: one block per batch index b. Recompute cur for flagged (b,o) with
// the EXACT round-3 arithmetic (single fp32 acc, k ascending FFMA, +bias at
// the end), then re-scan those neurons and overwrite out.
// ---------------------------------------------------------------------------
__global__ __launch_bounds__(256)
void snn_fixup(const float* __restrict__ X, const float* __restrict__ Wm,
               const float* __restrict__ bias, float* __restrict__ out)
{
    __shared__ unsigned short s_olist[O_DIM];
    __shared__ int s_cnt;

    const int b   = blockIdx.x;
    const int tid = threadIdx.x;

    if (tid == 0) s_cnt = 0;
    __syncthreads();

    const int total_flags = g_flag_cnt;
    for (int i = tid; i < total_flags; i += blockDim.x) {
        const int bo = g_flag_list[i];
        if ((bo >> 9) == b) {
            const int pos = atomicAdd(&s_cnt, 1);
            s_olist[pos] = (unsigned short)(bo & 511);
        }
    }
    __syncthreads();

    const int cnt = s_cnt;
    if (cnt == 0) return;

    // Phase A: recompute cur[t, b, o] for flagged o, all t. t-major tasks so
    // concurrent lanes share the x row in L1.
    const int ntasks = cnt * T_STEPS;
    for (int task = tid; task < ntasks; task += blockDim.x) {
        const int t  = task / cnt;
        const int o  = s_olist[task % cnt];
        const float* xr = X  + ((size_t)t * B_DIM + b) * I_DIM;
        const float* wr = Wm + (size_t)o * I_DIM;
        float acc = 0.0f;
        #pragma unroll 8
        for (int k = 0; k < I_DIM; ++k)
            acc = fmaf(xr[k], wr[k], acc);          // strict k-ascending chain
        g_cur[(size_t)t * BO + b * O_DIM + o] = acc + bias[o];
    }
    __threadfence_block();
    __syncthreads();

    // Phase B: re-scan flagged neurons (one thread per neuron).
    for (int i = tid; i < cnt; i += blockDim.x) {
        const int o  = s_olist[i];
        const size_t bo = (size_t)b * O_DIM + o;
        float mem = 0.0f;
        for (int t = 0; t < T_STEPS; ++t) {
            const float c = g_cur[(size_t)t * BO + bo];
            mem = BETA_F * mem + c;
            const float spk = (mem >= THRESH_F) ? 1.0f : 0.0f;
            out[(size_t)t * BO + bo] = spk;
            mem -= spk * THRESH_F;
        }
    }
}

// ---------------------------------------------------------------------------
extern "C" void kernel_launch(void* const* d_in, const int* in_sizes, int n_in,
                              void* d_out, int out_size) {
    const float* x    = (const float*)d_in[0]; // [T, B, I]
    const float* w    = (const float*)d_in[1]; // [O, I]
    const float* bias = (const float*)d_in[2]; // [O]
    float* out = (float*)d_out;                // [T, B, O]

    cudaFuncSetAttribute(snn_gemm_mma,
                         cudaFuncAttributeMaxDynamicSharedMemorySize, SMEM_ASK);

    snn_zero<<<1, 1>>>();                      // reset flag counter (capture-safe)

    dim3 grid(O_DIM / 128, M_DIM / 128);       // (4, 400), n fastest
    snn_gemm_mma<<<grid, 256, SMEM_ASK>>>(x, w, bias);

    snn_scan_flag<<<(BO / 4) / 256, 256>>>(out);

    snn_fixup<<<B_DIM, 256>>>(x, w, bias, out);
}

// round 10
// speedup vs baseline: 1.9213x; 1.9213x over previous
#include <cuda_runtime.h>
#include <cuda_bf16.h>
#include <cstdint>
#include <cstddef>

// Problem constants
#define T_STEPS 100
#define B_DIM   512
#define I_DIM   512
#define O_DIM   512
#define M_DIM   (T_STEPS * B_DIM)   // 51200
#define BO      (B_DIM * O_DIM)     // 262144

#define BETA_F   0.9f
#define THRESH_F 1.0f
#define DELTA_MEM 3e-4f             // flag margin: ~5x max |mem_tc - mem_seq|

// Scratch for input currents cur[T, B, O] (105 MB)
__device__ float g_cur[(size_t)T_STEPS * B_DIM * O_DIM];
// Flag worklist of ambiguous neurons (bo indices)
__device__ int g_flag_list[BO];
__device__ int g_flag_cnt;

// ---------------------------------------------------------------------------
// bf16x2 split GEMM on legacy tensor cores (mma.sync, sm_100 base ISA)
//   3 product GEMMs: (a1,b1), (a1,b2), (a2,b1). Dropped terms ~2^-18 rel;
//   flag margin covers the resulting spike ambiguity, fixup repairs it.
// ---------------------------------------------------------------------------
#define KC        64
#define NKC       (I_DIM / KC)        // 8
#define TILE_B    (128 * 128)         // 16384 B: 128 rows x 64 bf16 (128B rows)
#define BUF_B     (4 * TILE_B)        // 65536 B: a1 a2 b1 b2
#define SMEM_ASK  (1024 + 2 * BUF_B)  // 132096 B

static __device__ __forceinline__ uint32_t smem_u32(const void* p) {
    uint32_t a;
    asm("{ .reg .u64 t; cvta.to.shared.u64 t, %1; cvt.u32.u64 %0, t; }"
        : "=r"(a) : "l"(p));
    return a;
}

#define LDSM4(r0, r1, r2, r3, addr) \
    asm volatile("ldmatrix.sync.aligned.m8n8.x4.shared.b16 {%0,%1,%2,%3}, [%4];" \
        : "=r"(r0), "=r"(r1), "=r"(r2), "=r"(r3) : "r"(addr))

#define MMA_OP(D, A, b0, b1) \
    asm volatile("mma.sync.aligned.m16n8k16.row.col.f32.bf16.bf16.f32 " \
        "{%0,%1,%2,%3}, {%4,%5,%6,%7}, {%8,%9}, {%0,%1,%2,%3};" \
        : "+f"((D)[0]), "+f"((D)[1]), "+f"((D)[2]), "+f"((D)[3]) \
        : "r"((A)[0]), "r"((A)[1]), "r"((A)[2]), "r"((A)[3]), "r"(b0), "r"(b1))

static __device__ __forceinline__ uint32_t pack2(__nv_bfloat16 lo, __nv_bfloat16 hi) {
    __nv_bfloat162 p = __halves2bfloat162(lo, hi);
    return *reinterpret_cast<uint32_t*>(&p);
}

// Split a float4 into 2 bf16 components each; store 8B groups to 2 tiles.
static __device__ __forceinline__ void split_store2(char* tile0, uint32_t sw, float4 v) {
    float f0 = v.x, f1 = v.y, f2 = v.z, f3 = v.w;

    __nv_bfloat16 a0 = __float2bfloat16_rn(f0);
    __nv_bfloat16 a1 = __float2bfloat16_rn(f1);
    __nv_bfloat16 a2 = __float2bfloat16_rn(f2);
    __nv_bfloat16 a3 = __float2bfloat16_rn(f3);

    float r0 = f0 - __bfloat162float(a0);
    float r1 = f1 - __bfloat162float(a1);
    float r2 = f2 - __bfloat162float(a2);
    float r3 = f3 - __bfloat162float(a3);

    __nv_bfloat16 b0 = __float2bfloat16_rn(r0);
    __nv_bfloat16 b1 = __float2bfloat16_rn(r1);
    __nv_bfloat16 b2 = __float2bfloat16_rn(r2);
    __nv_bfloat16 b3 = __float2bfloat16_rn(r3);

    uint2 w1; w1.x = pack2(a0, a1); w1.y = pack2(a2, a3);
    uint2 w2; w2.x = pack2(b0, b1); w2.y = pack2(b2, b3);

    *reinterpret_cast<uint2*>(tile0 + sw)          = w1;
    *reinterpret_cast<uint2*>(tile0 + TILE_B + sw) = w2;
}

__global__ void __launch_bounds__(256)
snn_gemm_mma(const float* __restrict__ X, const float* __restrict__ Wm,
             const float* __restrict__ bias)
{
    extern __shared__ char smraw[];
    char* sm = (char*)((((uintptr_t)smraw) + 1023) & ~(uintptr_t)1023);
    const uint32_t sb = smem_u32(sm);

    const int tid  = threadIdx.x;
    const int warp = tid >> 5;
    const int lane = tid & 31;
    const int wm   = warp & 3;
    const int wn   = warp >> 2;

    const int n0 = blockIdx.x * 128;
    const int m0 = blockIdx.y * 128;

    const float* xs0 = X  + (size_t)m0 * I_DIM;
    const float* ws0 = Wm + (size_t)n0 * I_DIM;

    float acc[2][8][4] = {};
    float4 px[8], pw[8];

    auto loadc = [&](int kc) {
        #pragma unroll
        for (int i = 0; i < 8; ++i) {
            const int v   = i * 256 + tid;
            const int row = v >> 4;
            const int col = (v & 15) << 2;
            px[i] = *reinterpret_cast<const float4*>(
                xs0 + (size_t)row * I_DIM + kc * KC + col);
            pw[i] = *reinterpret_cast<const float4*>(
                ws0 + (size_t)row * I_DIM + kc * KC + col);
        }
    };

    auto storec = [&](char* bb) {
        #pragma unroll
        for (int i = 0; i < 8; ++i) {
            const int v   = i * 256 + tid;
            const int row = v >> 4;
            const int col = (v & 15) << 2;
            const uint32_t off = (uint32_t)(row * 128 + col * 2);
            const uint32_t sw  = off ^ ((off >> 3) & 0x70);
            split_store2(bb, sw, px[i]);
            split_store2(bb + 2 * TILE_B, sw, pw[i]);
        }
    };

    auto mmac = [&](uint32_t bbu) {
        const int PA[3] = {0, 0, 1};
        const int PB[3] = {0, 1, 0};
        #pragma unroll
        for (int p = 0; p < 3; ++p) {
            const uint32_t At = bbu + PA[p] * TILE_B;
            const uint32_t Bt = bbu + (2 + PB[p]) * TILE_B;
            #pragma unroll
            for (int ks = 0; ks < 4; ++ks) {
                uint32_t a[2][4];
                #pragma unroll
                for (int mt = 0; mt < 2; ++mt) {
                    const int row = wm * 32 + mt * 16 + (lane & 15);
                    const uint32_t off = (uint32_t)(row * 128 + ks * 32 + ((lane >> 4) << 4));
                    const uint32_t ad  = At + (off ^ ((off >> 3) & 0x70));
                    LDSM4(a[mt][0], a[mt][1], a[mt][2], a[mt][3], ad);
                }
                #pragma unroll
                for (int nq = 0; nq < 4; ++nq) {
                    const int g = lane >> 3, r = lane & 7;
                    const int nrow = wn * 64 + nq * 16 + ((g >> 1) << 3) + r;
                    const uint32_t off = (uint32_t)(nrow * 128 + ks * 32 + ((g & 1) << 4));
                    const uint32_t ad  = Bt + (off ^ ((off >> 3) & 0x70));
                    uint32_t b0, b1, b2, b3;
                    LDSM4(b0, b1, b2, b3, ad);
                    MMA_OP(acc[0][2 * nq],     a[0], b0, b1);
                    MMA_OP(acc[1][2 * nq],     a[1], b0, b1);
                    MMA_OP(acc[0][2 * nq + 1], a[0], b2, b3);
                    MMA_OP(acc[1][2 * nq + 1], a[1], b2, b3);
                }
            }
        }
    };

    loadc(0);
    for (int kc = 0; kc < NKC; ++kc) {
        char*    bb  = sm + (kc & 1) * BUF_B;
        uint32_t bbu = sb + (kc & 1) * BUF_B;
        storec(bb);
        __syncthreads();
        if (kc + 1 < NKC) loadc(kc + 1);
        mmac(bbu);
    }

    {
        const int rbase = m0 + wm * 32 + (lane >> 2);
        const int nb    = n0 + wn * 64 + (lane & 3) * 2;
        #pragma unroll
        for (int nt = 0; nt < 8; ++nt) {
            const int n = nb + nt * 8;
            const float2 bv = *reinterpret_cast<const float2*>(bias + n);
            #pragma unroll
            for (int mt = 0; mt < 2; ++mt) {
                const int r0 = rbase + mt * 16;
                float2 o0, o1;
                o0.x = acc[mt][nt][0] + bv.x;
                o0.y = acc[mt][nt][1] + bv.y;
                o1.x = acc[mt][nt][2] + bv.x;
                o1.y = acc[mt][nt][3] + bv.y;
                *reinterpret_cast<float2*>(&g_cur[(size_t)r0 * O_DIM + n])       = o0;
                *reinterpret_cast<float2*>(&g_cur[(size_t)(r0 + 8) * O_DIM + n]) = o1;
            }
        }
    }
}

// ---------------------------------------------------------------------------
// Zero the flag counter (pure kernel node; capture-safe).
// ---------------------------------------------------------------------------
__global__ void snn_zero() { g_flag_cnt = 0; }

// ---------------------------------------------------------------------------
// Scan + ambiguity flagging (single aggregated atomic per flagging thread).
// ---------------------------------------------------------------------------
__global__ __launch_bounds__(256)
void snn_scan_flag(float* __restrict__ out) {
    const int lane4 = blockIdx.x * blockDim.x + threadIdx.x;
    const size_t base = (size_t)lane4 * 4;

    float4 mem = make_float4(0.f, 0.f, 0.f, 0.f);
    int fl0 = 0, fl1 = 0, fl2 = 0, fl3 = 0;

    #pragma unroll 5
    for (int t = 0; t < T_STEPS; ++t) {
        const size_t off = (size_t)t * BO + base;
        float4 c = *reinterpret_cast<const float4*>(&g_cur[off]);

        mem.x = BETA_F * mem.x + c.x;
        mem.y = BETA_F * mem.y + c.y;
        mem.z = BETA_F * mem.z + c.z;
        mem.w = BETA_F * mem.w + c.w;

        fl0 |= (fabsf(mem.x - THRESH_F) < DELTA_MEM);
        fl1 |= (fabsf(mem.y - THRESH_F) < DELTA_MEM);
        fl2 |= (fabsf(mem.z - THRESH_F) < DELTA_MEM);
        fl3 |= (fabsf(mem.w - THRESH_F) < DELTA_MEM);

        float4 spk;
        spk.x = (mem.x >= THRESH_F) ? 1.0f : 0.0f;
        spk.y = (mem.y >= THRESH_F) ? 1.0f : 0.0f;
        spk.z = (mem.z >= THRESH_F) ? 1.0f : 0.0f;
        spk.w = (mem.w >= THRESH_F) ? 1.0f : 0.0f;

        *reinterpret_cast<float4*>(&out[off]) = spk;

        mem.x -= spk.x * THRESH_F;
        mem.y -= spk.y * THRESH_F;
        mem.z -= spk.z * THRESH_F;
        mem.w -= spk.w * THRESH_F;
    }

    const int nf = fl0 + fl1 + fl2 + fl3;
    if (nf) {
        int pos = atomicAdd(&g_flag_cnt, nf);
        if (fl0) g_flag_list[pos++] = (int)base + 0;
        if (fl1) g_flag_list[pos++] = (int)base + 1;
        if (fl2) g_flag_list[pos++] = (int)base + 2;
        if (fl3) g_flag_list[pos++] = (int)base + 3;
    }
}

// ---------------------------------------------------------------------------
// Fixup A: recompute cur for flagged neurons, all t. Global grid-stride over
// tasks, flagged-index fastest so warp lanes share t and (mostly) the x row.
// EXACT round-3 arithmetic: single fp32 acc, k ascending fmaf, +bias at end.
// ---------------------------------------------------------------------------
__global__ __launch_bounds__(256)
void snn_fix_cur(const float* __restrict__ X, const float* __restrict__ Wm,
                 const float* __restrict__ bias)
{
    const int F = g_flag_cnt;
    const int ntasks = F * T_STEPS;
    const int stride = gridDim.x * blockDim.x;

    for (int idx = blockIdx.x * blockDim.x + threadIdx.x; idx < ntasks; idx += stride) {
        const int t  = idx / F;
        const int fi = idx - t * F;
        const int bo = g_flag_list[fi];
        const int b  = bo >> 9;
        const int o  = bo & 511;

        const float4* xr = reinterpret_cast<const float4*>(
            X + ((size_t)t * B_DIM + b) * I_DIM);
        const float4* wr = reinterpret_cast<const float4*>(
            Wm + (size_t)o * I_DIM);

        float acc = 0.0f;
        #pragma unroll 4
        for (int k4 = 0; k4 < I_DIM / 4; ++k4) {
            const float4 xv = xr[k4];
            const float4 wv = wr[k4];
            acc = fmaf(xv.x, wv.x, acc);
            acc = fmaf(xv.y, wv.y, acc);
            acc = fmaf(xv.z, wv.z, acc);
            acc = fmaf(xv.w, wv.w, acc);
        }
        g_cur[(size_t)t * BO + bo] = acc + bias[o];
    }
}

// ---------------------------------------------------------------------------
// Fixup B: re-scan flagged neurons and overwrite out.
// ---------------------------------------------------------------------------
__global__ __launch_bounds__(256)
void snn_fix_scan(float* __restrict__ out) {
    const int F = g_flag_cnt;
    const int stride = gridDim.x * blockDim.x;

    for (int fi = blockIdx.x * blockDim.x + threadIdx.x; fi < F; fi += stride) {
        const int bo = g_flag_list[fi];
        float mem = 0.0f;
        for (int t = 0; t < T_STEPS; ++t) {
            const float c = g_cur[(size_t)t * BO + bo];
            mem = BETA_F * mem + c;
            const float spk = (mem >= THRESH_F) ? 1.0f : 0.0f;
            out[(size_t)t * BO + bo] = spk;
            mem -= spk * THRESH_F;
        }
    }
}

// ---------------------------------------------------------------------------
extern "C" void kernel_launch(void* const* d_in, const int* in_sizes, int n_in,
                              void* d_out, int out_size) {
    const float* x    = (const float*)d_in[0]; // [T, B, I]
    const float* w    = (const float*)d_in[1]; // [O, I]
    const float* bias = (const float*)d_in[2]; // [O]
    float* out = (float*)d_out;                // [T, B, O]

    cudaFuncSetAttribute(snn_gemm_mma,
                         cudaFuncAttributeMaxDynamicSharedMemorySize, SMEM_ASK);

    snn_zero<<<1, 1>>>();

    dim3 grid(O_DIM / 128, M_DIM / 128);       // (4, 400), n fastest
    snn_gemm_mma<<<grid, 256, SMEM_ASK>>>(x, w, bias);

    snn_scan_flag<<<(BO / 4) / 256, 256>>>(out);

    snn_fix_cur<<<2048, 256>>>(x, w, bias);    // grid-stride over F*100 tasks
    snn_fix_scan<<<64, 256>>>(out);            // grid-stride over F neurons
}

// round 11
// speedup vs baseline: 2.1260x; 1.1065x over previous
#include <cuda_runtime.h>
#include <cuda_bf16.h>
#include <cstdint>
#include <cstddef>

// Problem constants
#define T_STEPS 100
#define B_DIM   512
#define I_DIM   512
#define O_DIM   512
#define M_DIM   (T_STEPS * B_DIM)   // 51200
#define BO      (B_DIM * O_DIM)     // 262144

#define BETA_F   0.9f
#define THRESH_F 1.0f
#define DELTA_MEM 1.5e-4f           // flag margin: ~3.5x max |mem_tc - mem_seq|

// Scratch for input currents cur[T, B, O] (105 MB)
__device__ float g_cur[(size_t)T_STEPS * B_DIM * O_DIM];
// Flag worklist of ambiguous neurons (bo indices)
__device__ int g_flag_list[BO];
__device__ int g_flag_cnt;

// ---------------------------------------------------------------------------
// bf16x2 split GEMM, warp-specialized: warps 0-7 run mma.sync on chunk k
// while warps 8-11 split/store chunk k+1 (double-buffered smem).
// 3 product GEMMs: (a1,b1), (a1,b2), (a2,b1); dropped term ~2^-18 rel.
// ---------------------------------------------------------------------------
#define KC        64
#define NKC       (I_DIM / KC)        // 8
#define TILE_B    (128 * 128)         // 16384 B: 128 rows x 64 bf16 (128B rows)
#define BUF_B     (4 * TILE_B)        // 65536 B: a1 a2 b1 b2
#define SMEM_ASK  (1024 + 2 * BUF_B)  // 132096 B
#define GEMM_THREADS 384

static __device__ __forceinline__ uint32_t smem_u32(const void* p) {
    uint32_t a;
    asm("{ .reg .u64 t; cvta.to.shared.u64 t, %1; cvt.u32.u64 %0, t; }"
        : "=r"(a) : "l"(p));
    return a;
}

#define LDSM4(r0, r1, r2, r3, addr) \
    asm volatile("ldmatrix.sync.aligned.m8n8.x4.shared.b16 {%0,%1,%2,%3}, [%4];" \
        : "=r"(r0), "=r"(r1), "=r"(r2), "=r"(r3) : "r"(addr))

#define MMA_OP(D, A, b0, b1) \
    asm volatile("mma.sync.aligned.m16n8k16.row.col.f32.bf16.bf16.f32 " \
        "{%0,%1,%2,%3}, {%4,%5,%6,%7}, {%8,%9}, {%0,%1,%2,%3};" \
        : "+f"((D)[0]), "+f"((D)[1]), "+f"((D)[2]), "+f"((D)[3]) \
        : "r"((A)[0]), "r"((A)[1]), "r"((A)[2]), "r"((A)[3]), "r"(b0), "r"(b1))

static __device__ __forceinline__ uint32_t pack2(__nv_bfloat16 lo, __nv_bfloat16 hi) {
    __nv_bfloat162 p = __halves2bfloat162(lo, hi);
    return *reinterpret_cast<uint32_t*>(&p);
}

// Split a float4 into 2 bf16 components each; store 8B groups to 2 tiles.
static __device__ __forceinline__ void split_store2(char* tile0, uint32_t sw, float4 v) {
    float f0 = v.x, f1 = v.y, f2 = v.z, f3 = v.w;

    __nv_bfloat16 a0 = __float2bfloat16_rn(f0);
    __nv_bfloat16 a1 = __float2bfloat16_rn(f1);
    __nv_bfloat16 a2 = __float2bfloat16_rn(f2);
    __nv_bfloat16 a3 = __float2bfloat16_rn(f3);

    float r0 = f0 - __bfloat162float(a0);
    float r1 = f1 - __bfloat162float(a1);
    float r2 = f2 - __bfloat162float(a2);
    float r3 = f3 - __bfloat162float(a3);

    __nv_bfloat16 b0 = __float2bfloat16_rn(r0);
    __nv_bfloat16 b1 = __float2bfloat16_rn(r1);
    __nv_bfloat16 b2 = __float2bfloat16_rn(r2);
    __nv_bfloat16 b3 = __float2bfloat16_rn(r3);

    uint2 w1; w1.x = pack2(a0, a1); w1.y = pack2(a2, a3);
    uint2 w2; w2.x = pack2(b0, b1); w2.y = pack2(b2, b3);

    *reinterpret_cast<uint2*>(tile0 + sw)          = w1;
    *reinterpret_cast<uint2*>(tile0 + TILE_B + sw) = w2;
}

__global__ void __launch_bounds__(GEMM_THREADS)
snn_gemm_mma(const float* __restrict__ X, const float* __restrict__ Wm,
             const float* __restrict__ bias)
{
    extern __shared__ char smraw[];
    char* sm = (char*)((((uintptr_t)smraw) + 1023) & ~(uintptr_t)1023);
    const uint32_t sb = smem_u32(sm);

    const int tid  = threadIdx.x;
    const int warp = tid >> 5;
    const int lane = tid & 31;

    const int n0 = blockIdx.x * 128;
    const int m0 = blockIdx.y * 128;

    const float* xs0 = X  + (size_t)m0 * I_DIM;
    const float* ws0 = Wm + (size_t)n0 * I_DIM;

    // Producer: warps 8-11 (128 threads) load fp32, split to bf16x2, store.
    auto produce = [&](int kc, char* bb) {
        const int ptid = tid - 256;              // 0..127
        const float* xs = xs0 + kc * KC;
        const float* ws = ws0 + kc * KC;
        #pragma unroll 4
        for (int i = 0; i < 16; ++i) {
            const int v   = i * 128 + ptid;      // 0..2047
            const int row = v >> 4;              // 0..127
            const int col = (v & 15) << 2;       // 0,4,...,60
            const uint32_t off = (uint32_t)(row * 128 + col * 2);
            const uint32_t sw  = off ^ ((off >> 3) & 0x70);
            const float4 xv = *reinterpret_cast<const float4*>(
                xs + (size_t)row * I_DIM + col);
            split_store2(bb, sw, xv);
            const float4 wv = *reinterpret_cast<const float4*>(
                ws + (size_t)row * I_DIM + col);
            split_store2(bb + 2 * TILE_B, sw, wv);
        }
    };

    if (warp >= 8) {
        // ---- producer path ----
        produce(0, sm);
        __syncthreads();
        for (int kc = 0; kc < NKC; ++kc) {
            if (kc + 1 < NKC) produce(kc + 1, sm + ((kc + 1) & 1) * BUF_B);
            __syncthreads();
        }
        return;   // no epilogue for producers
    }

    // ---- consumer path: warps 0-7 ----
    const int wm = warp & 3;
    const int wn = warp >> 2;

    float acc[2][8][4] = {};

    __syncthreads();   // matches producer's post-chunk0 sync

    for (int kc = 0; kc < NKC; ++kc) {
        const uint32_t bbu = sb + (kc & 1) * BUF_B;
        const int PA[3] = {0, 0, 1};
        const int PB[3] = {0, 1, 0};
        #pragma unroll
        for (int p = 0; p < 3; ++p) {
            const uint32_t At = bbu + PA[p] * TILE_B;
            const uint32_t Bt = bbu + (2 + PB[p]) * TILE_B;
            #pragma unroll
            for (int ks = 0; ks < 4; ++ks) {
                uint32_t a[2][4];
                #pragma unroll
                for (int mt = 0; mt < 2; ++mt) {
                    const int row = wm * 32 + mt * 16 + (lane & 15);
                    const uint32_t off = (uint32_t)(row * 128 + ks * 32 + ((lane >> 4) << 4));
                    const uint32_t ad  = At + (off ^ ((off >> 3) & 0x70));
                    LDSM4(a[mt][0], a[mt][1], a[mt][2], a[mt][3], ad);
                }
                #pragma unroll
                for (int nq = 0; nq < 4; ++nq) {
                    const int g = lane >> 3, r = lane & 7;
                    const int nrow = wn * 64 + nq * 16 + ((g >> 1) << 3) + r;
                    const uint32_t off = (uint32_t)(nrow * 128 + ks * 32 + ((g & 1) << 4));
                    const uint32_t ad  = Bt + (off ^ ((off >> 3) & 0x70));
                    uint32_t b0, b1, b2, b3;
                    LDSM4(b0, b1, b2, b3, ad);
                    MMA_OP(acc[0][2 * nq],     a[0], b0, b1);
                    MMA_OP(acc[1][2 * nq],     a[1], b0, b1);
                    MMA_OP(acc[0][2 * nq + 1], a[0], b2, b3);
                    MMA_OP(acc[1][2 * nq + 1], a[1], b2, b3);
                }
            }
        }
        __syncthreads();   // chunk k consumed; producer's k+1 now visible
    }

    // Epilogue: write acc + bias to g_cur.
    {
        const int rbase = m0 + wm * 32 + (lane >> 2);
        const int nb    = n0 + wn * 64 + (lane & 3) * 2;
        #pragma unroll
        for (int nt = 0; nt < 8; ++nt) {
            const int n = nb + nt * 8;
            const float2 bv = *reinterpret_cast<const float2*>(bias + n);
            #pragma unroll
            for (int mt = 0; mt < 2; ++mt) {
                const int r0 = rbase + mt * 16;
                float2 o0, o1;
                o0.x = acc[mt][nt][0] + bv.x;
                o0.y = acc[mt][nt][1] + bv.y;
                o1.x = acc[mt][nt][2] + bv.x;
                o1.y = acc[mt][nt][3] + bv.y;
                *reinterpret_cast<float2*>(&g_cur[(size_t)r0 * O_DIM + n])       = o0;
                *reinterpret_cast<float2*>(&g_cur[(size_t)(r0 + 8) * O_DIM + n]) = o1;
            }
        }
    }
}

// ---------------------------------------------------------------------------
// Zero the flag counter (pure kernel node; capture-safe).
// ---------------------------------------------------------------------------
__global__ void snn_zero() { g_flag_cnt = 0; }

// ---------------------------------------------------------------------------
// Scan + ambiguity flagging (single aggregated atomic per flagging thread).
// ---------------------------------------------------------------------------
__global__ __launch_bounds__(256)
void snn_scan_flag(float* __restrict__ out) {
    const int lane4 = blockIdx.x * blockDim.x + threadIdx.x;
    const size_t base = (size_t)lane4 * 4;

    float4 mem = make_float4(0.f, 0.f, 0.f, 0.f);
    int fl0 = 0, fl1 = 0, fl2 = 0, fl3 = 0;

    #pragma unroll 5
    for (int t = 0; t < T_STEPS; ++t) {
        const size_t off = (size_t)t * BO + base;
        float4 c = *reinterpret_cast<const float4*>(&g_cur[off]);

        mem.x = BETA_F * mem.x + c.x;
        mem.y = BETA_F * mem.y + c.y;
        mem.z = BETA_F * mem.z + c.z;
        mem.w = BETA_F * mem.w + c.w;

        fl0 |= (fabsf(mem.x - THRESH_F) < DELTA_MEM);
        fl1 |= (fabsf(mem.y - THRESH_F) < DELTA_MEM);
        fl2 |= (fabsf(mem.z - THRESH_F) < DELTA_MEM);
        fl3 |= (fabsf(mem.w - THRESH_F) < DELTA_MEM);

        float4 spk;
        spk.x = (mem.x >= THRESH_F) ? 1.0f : 0.0f;
        spk.y = (mem.y >= THRESH_F) ? 1.0f : 0.0f;
        spk.z = (mem.z >= THRESH_F) ? 1.0f : 0.0f;
        spk.w = (mem.w >= THRESH_F) ? 1.0f : 0.0f;

        *reinterpret_cast<float4*>(&out[off]) = spk;

        mem.x -= spk.x * THRESH_F;
        mem.y -= spk.y * THRESH_F;
        mem.z -= spk.z * THRESH_F;
        mem.w -= spk.w * THRESH_F;
    }

    const int nf = fl0 + fl1 + fl2 + fl3;
    if (nf) {
        int pos = atomicAdd(&g_flag_cnt, nf);
        if (fl0) g_flag_list[pos++] = (int)base + 0;
        if (fl1) g_flag_list[pos++] = (int)base + 1;
        if (fl2) g_flag_list[pos++] = (int)base + 2;
        if (fl3) g_flag_list[pos++] = (int)base + 3;
    }
}

// ---------------------------------------------------------------------------
// Fixup A: warp-per-(neuron, t-group). All 32 lanes share one flagged neuron
// (same b, o -> w row loads are broadcast; 1 wavefront instead of 32) and
// cover 32 consecutive t. EXACT round-3 arithmetic per (t, neuron): single
// fp32 acc, k ascending fmaf, +bias at end.
// ---------------------------------------------------------------------------
__global__ __launch_bounds__(256)
void snn_fix_cur(const float* __restrict__ X, const float* __restrict__ Wm,
                 const float* __restrict__ bias)
{
    const int F = g_flag_cnt;
    const int nwtasks = F * 4;                   // 4 t-groups of 32 per neuron
    const int warps_total = (gridDim.x * blockDim.x) >> 5;
    const int gwarp = (blockIdx.x * blockDim.x + threadIdx.x) >> 5;
    const int lane  = threadIdx.x & 31;

    for (int wt = gwarp; wt < nwtasks; wt += warps_total) {
        const int fi = wt >> 2;
        const int tg = wt & 3;
        const int t  = tg * 32 + lane;

        const int bo = g_flag_list[fi];
        const int b  = bo >> 9;
        const int o  = bo & 511;

        const float4* wr = reinterpret_cast<const float4*>(Wm + (size_t)o * I_DIM);
        const float bz = bias[o];

        if (t < T_STEPS) {
            const float4* xr = reinterpret_cast<const float4*>(
                X + ((size_t)t * B_DIM + b) * I_DIM);
            float acc = 0.0f;
            #pragma unroll 4
            for (int k4 = 0; k4 < I_DIM / 4; ++k4) {
                const float4 xv = xr[k4];
                const float4 wv = wr[k4];       // broadcast across lanes
                acc = fmaf(xv.x, wv.x, acc);
                acc = fmaf(xv.y, wv.y, acc);
                acc = fmaf(xv.z, wv.z, acc);
                acc = fmaf(xv.w, wv.w, acc);
            }
            g_cur[(size_t)t * BO + bo] = acc + bz;
        }
    }
}

// ---------------------------------------------------------------------------
// Fixup B: re-scan flagged neurons and overwrite out.
// ---------------------------------------------------------------------------
__global__ __launch_bounds__(256)
void snn_fix_scan(float* __restrict__ out) {
    const int F = g_flag_cnt;
    const int stride = gridDim.x * blockDim.x;

    for (int fi = blockIdx.x * blockDim.x + threadIdx.x; fi < F; fi += stride) {
        const int bo = g_flag_list[fi];
        float mem = 0.0f;
        for (int t = 0; t < T_STEPS; ++t) {
            const float c = g_cur[(size_t)t * BO + bo];
            mem = BETA_F * mem + c;
            const float spk = (mem >= THRESH_F) ? 1.0f : 0.0f;
            out[(size_t)t * BO + bo] = spk;
            mem -= spk * THRESH_F;
        }
    }
}

// ---------------------------------------------------------------------------
extern "C" void kernel_launch(void* const* d_in, const int* in_sizes, int n_in,
                              void* d_out, int out_size) {
    const float* x    = (const float*)d_in[0]; // [T, B, I]
    const float* w    = (const float*)d_in[1]; // [O, I]
    const float* bias = (const float*)d_in[2]; // [O]
    float* out = (float*)d_out;                // [T, B, O]

    cudaFuncSetAttribute(snn_gemm_mma,
                         cudaFuncAttributeMaxDynamicSharedMemorySize, SMEM_ASK);

    snn_zero<<<1, 1>>>();

    dim3 grid(O_DIM / 128, M_DIM / 128);       // (4, 400), n fastest
    snn_gemm_mma<<<grid, GEMM_THREADS, SMEM_ASK>>>(x, w, bias);

    snn_scan_flag<<<(BO / 4) / 256, 256>>>(out);

    snn_fix_cur<<<1024, 256>>>(x, w, bias);    // warp-per-(neuron, t-group)
    snn_fix_scan<<<64, 256>>>(out);            // grid-stride over F neurons
}